// round 3
// baseline (speedup 1.0000x reference)
#include <cuda_runtime.h>
#include <math.h>

#define S_DIM 512
#define N_DIM 384
#define CIN   64
#define CZ    128
#define H_DIM 8
#define C_DIM 32
#define D_DIM 256
#define INF_  1e9f
#define EPS_  1e-5f
#define MROWS (S_DIM*N_DIM)   // 196608

// ---- scratch (static device arrays: no allocations allowed) ----
__device__ float g_w [(size_t)H_DIM*N_DIM*N_DIM];          // attn weights [h][q][k]
__device__ float g_mn[(size_t)MROWS*CIN];                   // LN(m)
__device__ float g_v [(size_t)H_DIM*N_DIM*S_DIM*C_DIM];     // v  [h][k][s][c]
__device__ float g_g [(size_t)MROWS*D_DIM];                 // gate [s*N+n][256]
__device__ float g_o [(size_t)MROWS*D_DIM];                 // o    [s*N+q][256]

// ============================================================
// Kernel 1: LN(z) + logits (warp per (q,k) row of 128)
// ============================================================
__global__ void k_lnz_logits(const float* __restrict__ z, const float* __restrict__ mask,
                             const float* __restrict__ gamma_z, const float* __restrict__ beta_z,
                             const float* __restrict__ w_z, const float* __restrict__ b_z)
{
    int gw   = (blockIdx.x * blockDim.x + threadIdx.x) >> 5;
    int lane = threadIdx.x & 31;
    if (gw >= N_DIM * N_DIM) return;
    int q = gw / N_DIM, k = gw % N_DIM;
    const float* zp = z + (size_t)gw * CZ;

    float x0 = zp[lane], x1 = zp[lane+32], x2 = zp[lane+64], x3 = zp[lane+96];
    float s  = x0+x1+x2+x3;
    float s2 = x0*x0 + x1*x1 + x2*x2 + x3*x3;
    #pragma unroll
    for (int o = 16; o; o >>= 1) {
        s  += __shfl_xor_sync(0xffffffffu, s,  o);
        s2 += __shfl_xor_sync(0xffffffffu, s2, o);
    }
    float mu  = s * (1.0f / CZ);
    float inv = rsqrtf(s2 * (1.0f / CZ) - mu*mu + EPS_);
    float n0 = (x0-mu)*inv*gamma_z[lane]    + beta_z[lane];
    float n1 = (x1-mu)*inv*gamma_z[lane+32] + beta_z[lane+32];
    float n2 = (x2-mu)*inv*gamma_z[lane+64] + beta_z[lane+64];
    float n3 = (x3-mu)*inv*gamma_z[lane+96] + beta_z[lane+96];

    float acc[H_DIM];
    #pragma unroll
    for (int h = 0; h < H_DIM; h++) {
        acc[h] = n0 * w_z[lane*H_DIM + h]
               + n1 * w_z[(lane+32)*H_DIM + h]
               + n2 * w_z[(lane+64)*H_DIM + h]
               + n3 * w_z[(lane+96)*H_DIM + h];
        #pragma unroll
        for (int o = 16; o; o >>= 1)
            acc[h] += __shfl_xor_sync(0xffffffffu, acc[h], o);
    }
    if (lane == 0) {
        float bias = INF_ * (mask[gw] - 1.0f);
        #pragma unroll
        for (int h = 0; h < H_DIM; h++)
            g_w[((size_t)h*N_DIM + q)*N_DIM + k] = acc[h] + b_z[h] + bias;
    }
}

// ============================================================
// Kernel 2: softmax over k for each (h,q) row (in place in g_w)
// ============================================================
__global__ void k_softmax()
{
    int row = blockIdx.x;
    float* p = g_w + (size_t)row * N_DIM;
    int tid = threadIdx.x;  // 128 threads, 3 elems each
    __shared__ float red[128];

    float v0 = p[tid], v1 = p[tid+128], v2 = p[tid+256];
    float mx = fmaxf(v0, fmaxf(v1, v2));
    red[tid] = mx; __syncthreads();
    for (int o = 64; o; o >>= 1) { if (tid < o) red[tid] = fmaxf(red[tid], red[tid+o]); __syncthreads(); }
    mx = red[0]; __syncthreads();

    float e0 = expf(v0-mx), e1 = expf(v1-mx), e2 = expf(v2-mx);
    red[tid] = e0 + e1 + e2; __syncthreads();
    for (int o = 64; o; o >>= 1) { if (tid < o) red[tid] += red[tid+o]; __syncthreads(); }
    float inv = 1.0f / red[0];

    p[tid] = e0*inv; p[tid+128] = e1*inv; p[tid+256] = e2*inv;
}

// ============================================================
// Kernel 3: LN(m) -> g_mn (warp per row of 64)
// ============================================================
__global__ void k_lnm(const float* __restrict__ m,
                      const float* __restrict__ gamma_m, const float* __restrict__ beta_m)
{
    int gw   = (blockIdx.x * blockDim.x + threadIdx.x) >> 5;
    int lane = threadIdx.x & 31;
    if (gw >= MROWS) return;
    const float* mp = m + (size_t)gw * CIN;
    float a = mp[lane], b = mp[lane+32];
    float s = a + b, s2 = a*a + b*b;
    #pragma unroll
    for (int o = 16; o; o >>= 1) {
        s  += __shfl_xor_sync(0xffffffffu, s,  o);
        s2 += __shfl_xor_sync(0xffffffffu, s2, o);
    }
    float mu  = s * (1.0f / CIN);
    float inv = rsqrtf(s2 * (1.0f / CIN) - mu*mu + EPS_);
    float* op = g_mn + (size_t)gw * CIN;
    op[lane]    = (a-mu)*inv*gamma_m[lane]    + beta_m[lane];
    op[lane+32] = (b-mu)*inv*gamma_m[lane+32] + beta_m[lane+32];
}

// ============================================================
// Kernel 4: GEMM mn[196608,64] @ [w_v | w_g][64,512]
//   epilogue: j<256 -> +b_v, scatter to g_v[h][k][s][c]
//             j>=256 -> sigmoid(+b_g) -> g_g[row][j-256]
// ============================================================
__global__ __launch_bounds__(256) void k_gemm_vg(const float* __restrict__ w_v, const float* __restrict__ b_v,
                                                 const float* __restrict__ w_g, const float* __restrict__ b_g)
{
    const int BM = 128, BN = 64, BK = 16;
    __shared__ __align__(16) float As[BK][BM];
    __shared__ __align__(16) float Bs[BK][BN];
    int tid = threadIdx.x;
    int tx  = tid & 15, ty = tid >> 4;
    int m0  = blockIdx.y * BM;
    int n0  = blockIdx.x * BN;
    int ar  = tid >> 2, ac = (tid & 3) * 4;
    int br  = tid >> 4, bc = (tid & 15) * 4;
    float acc[8][4] = {};

    for (int k0 = 0; k0 < CIN; k0 += BK) {
        #pragma unroll
        for (int half = 0; half < BM; half += 64) {
            float4 av = *(const float4*)(g_mn + (size_t)(m0+ar+half)*CIN + k0 + ac);
            As[ac+0][ar+half] = av.x; As[ac+1][ar+half] = av.y;
            As[ac+2][ar+half] = av.z; As[ac+3][ar+half] = av.w;
        }
        #pragma unroll
        for (int u = 0; u < 4; u++) {
            int j = n0 + bc + u;
            Bs[br][bc+u] = (j < D_DIM) ? w_v[(k0+br)*D_DIM + j]
                                       : w_g[(k0+br)*D_DIM + (j - D_DIM)];
        }
        __syncthreads();
        #pragma unroll
        for (int kk = 0; kk < BK; kk++) {
            float rA[8], rB[4];
            #pragma unroll
            for (int i = 0; i < 8; i++) rA[i] = As[kk][ty*8+i];
            #pragma unroll
            for (int j = 0; j < 4; j++) rB[j] = Bs[kk][tx*4+j];
            #pragma unroll
            for (int i = 0; i < 8; i++)
                #pragma unroll
                for (int j = 0; j < 4; j++)
                    acc[i][j] += rA[i] * rB[j];
        }
        __syncthreads();
    }

    #pragma unroll
    for (int i = 0; i < 8; i++) {
        int row = m0 + ty*8 + i;
        int sI = row / N_DIM, kI = row % N_DIM;   // row = s*N + n
        #pragma unroll
        for (int j = 0; j < 4; j++) {
            int col = n0 + tx*4 + j;
            if (col < D_DIM) {
                float val = acc[i][j] + b_v[col];
                g_v[(((size_t)(col >> 5)*N_DIM + kI)*S_DIM + sI)*C_DIM + (col & 31)] = val;
            } else {
                int jg = col - D_DIM;
                float t = acc[i][j] + b_g[jg];
                g_g[(size_t)row*D_DIM + jg] = 1.0f / (1.0f + expf(-t));
            }
        }
    }
}

// ============================================================
// Kernel 5: per-head GEMM  w_h[384,384] @ v_h[384,16384] -> o
//   epilogue scatter: g_o[(s*N+q)*256 + h*32 + c]
// ============================================================
__global__ __launch_bounds__(256) void k_gemm_att()
{
    const int BM = 128, BN = 64, BK = 16;
    __shared__ __align__(16) float As[BK][BM];
    __shared__ __align__(16) float Bs[BK][BN];
    int tid = threadIdx.x;
    int tx  = tid & 15, ty = tid >> 4;
    int h   = blockIdx.z;
    int m0  = blockIdx.y * BM;     // q tile (M=384)
    int n0  = blockIdx.x * BN;     // n tile (N=16384)
    const float* A = g_w + (size_t)h * N_DIM * N_DIM;
    const float* B = g_v + (size_t)h * N_DIM * S_DIM * C_DIM;
    const int lda = N_DIM, ldb = S_DIM * C_DIM;
    int ar = tid >> 2, ac = (tid & 3) * 4;
    int br = tid >> 4, bc = (tid & 15) * 4;
    float acc[8][4] = {};

    for (int k0 = 0; k0 < N_DIM; k0 += BK) {
        #pragma unroll
        for (int half = 0; half < BM; half += 64) {
            float4 av = *(const float4*)(A + (size_t)(m0+ar+half)*lda + k0 + ac);
            As[ac+0][ar+half] = av.x; As[ac+1][ar+half] = av.y;
            As[ac+2][ar+half] = av.z; As[ac+3][ar+half] = av.w;
        }
        float4 bv = *(const float4*)(B + (size_t)(k0+br)*ldb + n0 + bc);
        *(float4*)&Bs[br][bc] = bv;
        __syncthreads();
        #pragma unroll
        for (int kk = 0; kk < BK; kk++) {
            float rA[8], rB[4];
            #pragma unroll
            for (int i = 0; i < 8; i++) rA[i] = As[kk][ty*8+i];
            #pragma unroll
            for (int j = 0; j < 4; j++) rB[j] = Bs[kk][tx*4+j];
            #pragma unroll
            for (int i = 0; i < 8; i++)
                #pragma unroll
                for (int j = 0; j < 4; j++)
                    acc[i][j] += rA[i] * rB[j];
        }
        __syncthreads();
    }

    #pragma unroll
    for (int i = 0; i < 8; i++) {
        int q = m0 + ty*8 + i;
        #pragma unroll
        for (int j = 0; j < 4; j++) {
            int n  = n0 + tx*4 + j;
            int sI = n >> 5, c = n & 31;
            g_o[((size_t)sI*N_DIM + q)*D_DIM + h*C_DIM + c] = acc[i][j];
        }
    }
}

// ============================================================
// Kernel 6: GEMM (o*g)[196608,256] @ w_o[256,64] + b_o -> out
//   gating fused into the A-tile load
// ============================================================
__global__ __launch_bounds__(256) void k_gemm_out(const float* __restrict__ w_o,
                                                  const float* __restrict__ b_o,
                                                  float* __restrict__ out)
{
    const int BM = 128, BN = 64, BK = 16;
    __shared__ __align__(16) float As[BK][BM];
    __shared__ __align__(16) float Bs[BK][BN];
    int tid = threadIdx.x;
    int tx  = tid & 15, ty = tid >> 4;
    int m0  = blockIdx.y * BM;
    int ar  = tid >> 2, ac = (tid & 3) * 4;
    int br  = tid >> 4, bc = (tid & 15) * 4;
    float acc[8][4] = {};

    for (int k0 = 0; k0 < D_DIM; k0 += BK) {
        #pragma unroll
        for (int half = 0; half < BM; half += 64) {
            size_t base = (size_t)(m0+ar+half)*D_DIM + k0 + ac;
            float4 ao = *(const float4*)(g_o + base);
            float4 ag = *(const float4*)(g_g + base);
            As[ac+0][ar+half] = ao.x*ag.x; As[ac+1][ar+half] = ao.y*ag.y;
            As[ac+2][ar+half] = ao.z*ag.z; As[ac+3][ar+half] = ao.w*ag.w;
        }
        float4 bv = *(const float4*)(w_o + (k0+br)*BN + bc);
        *(float4*)&Bs[br][bc] = bv;
        __syncthreads();
        #pragma unroll
        for (int kk = 0; kk < BK; kk++) {
            float rA[8], rB[4];
            #pragma unroll
            for (int i = 0; i < 8; i++) rA[i] = As[kk][ty*8+i];
            #pragma unroll
            for (int j = 0; j < 4; j++) rB[j] = Bs[kk][tx*4+j];
            #pragma unroll
            for (int i = 0; i < 8; i++)
                #pragma unroll
                for (int j = 0; j < 4; j++)
                    acc[i][j] += rA[i] * rB[j];
        }
        __syncthreads();
    }

    #pragma unroll
    for (int i = 0; i < 8; i++) {
        int row = m0 + ty*8 + i;
        #pragma unroll
        for (int j = 0; j < 4; j++) {
            int col = tx*4 + j;
            out[(size_t)row*CIN + col] = acc[i][j] + b_o[col];
        }
    }
}

// ============================================================
extern "C" void kernel_launch(void* const* d_in, const int* in_sizes, int n_in,
                              void* d_out, int out_size)
{
    const float* m       = (const float*)d_in[0];
    const float* z       = (const float*)d_in[1];
    const float* mask    = (const float*)d_in[2];
    const float* gamma_m = (const float*)d_in[3];
    const float* beta_m  = (const float*)d_in[4];
    const float* gamma_z = (const float*)d_in[5];
    const float* beta_z  = (const float*)d_in[6];
    const float* w_z     = (const float*)d_in[7];
    const float* b_z     = (const float*)d_in[8];
    const float* w_v     = (const float*)d_in[9];
    const float* b_v     = (const float*)d_in[10];
    const float* w_g     = (const float*)d_in[11];
    const float* b_g     = (const float*)d_in[12];
    const float* w_o     = (const float*)d_in[13];
    const float* b_o     = (const float*)d_in[14];
    float* out = (float*)d_out;

    // 1. LN(z) + logits: 147456 (q,k) warps, 8 warps/block
    k_lnz_logits<<<(N_DIM*N_DIM)/8, 256>>>(z, mask, gamma_z, beta_z, w_z, b_z);
    // 2. softmax over k, one block per (h,q)
    k_softmax<<<H_DIM*N_DIM, 128>>>();
    // 3. LN(m): 196608 warps, 8 warps/block
    k_lnm<<<MROWS/8, 256>>>(m, gamma_m, beta_m);
    // 4. v/g projection GEMM: N=512 (8 tiles of 64), M=196608 (1536 tiles of 128)
    k_gemm_vg<<<dim3(8, MROWS/128), 256>>>(w_v, b_v, w_g, b_g);
    // 5. attention GEMM per head: N=16384 (256), M=384 (3), H=8
    k_gemm_att<<<dim3(256, 3, 8), 256>>>();
    // 6. gated output projection: N=64 (1 tile), M=196608 (1536)
    k_gemm_out<<<dim3(1, MROWS/128), 256>>>(w_o, b_o, out);
}